// round 5
// baseline (speedup 1.0000x reference)
#include <cuda_runtime.h>
#include <cstdint>
#include <cstddef>

#define MAX_N 50000
#define MAX_E 800000
#define TILE_E 256
#define XSTRIDE 260   // floats; 260*4=1040B, 16B-aligned rows, bank-shift 4/row

// Scratch (static device globals — no runtime allocation)
__device__ float g_s[MAX_N * 64];            // per-node s0(16) + s1(16x3)
__device__ float g_agg[MAX_N * 176];         // m0a16|m0b16|m1a48|m1b48|m1c48
__device__ float g_wf[(size_t)MAX_E * 80];   // per-edge MLP out (edge order)
__device__ int   g_eidx[MAX_E];              // CSR edge list
__device__ int   g_deg[MAX_N];
__device__ int   g_off[MAX_N + 1];
__device__ int   g_cur[MAX_N];

// ---------- packed fp32x2 helpers (sm_103a) ----------
__device__ __forceinline__ unsigned long long pk2s(float a) {
    unsigned long long r;
    asm("mov.b64 %0, {%1,%1};" : "=l"(r) : "f"(a));
    return r;
}
__device__ __forceinline__ void upk2(unsigned long long v, float& a, float& b) {
    asm("mov.b64 {%0,%1}, %2;" : "=f"(a), "=f"(b) : "l"(v));
}
__device__ __forceinline__ void ff2(unsigned long long& d, unsigned long long a, unsigned long long b) {
    asm("fma.rn.f32x2 %0, %1, %2, %0;" : "+l"(d) : "l"(a), "l"(b));
}
__device__ __forceinline__ float silu(float v) {
    return v / (1.f + __expf(-v));
}

// ======================================================================
// Kernel: self-interaction s = FCTP(x, attr; W_si)  + zero degree array
// ======================================================================
__global__ void __launch_bounds__(128) node_pre_kernel(
    const float* __restrict__ xin, const float* __restrict__ attr,
    const float* __restrict__ Wsi0, const float* __restrict__ Wsi1, int N)
{
    __shared__ float w0[256], w1[256];
    int t = threadIdx.x;
    if (t < 128) { w0[t] = Wsi0[t]; w0[t + 128] = Wsi0[t + 128];
                   w1[t] = Wsi1[t]; w1[t + 128] = Wsi1[t + 128]; }
    __syncthreads();
    int n = blockIdx.x * 128 + t;
    if (n >= N) return;

    g_deg[n] = 0;

    float x[64];
    const float4* xp = (const float4*)(xin + (size_t)n * 64);
#pragma unroll
    for (int q = 0; q < 16; q++) {
        float4 v = __ldg(xp + q);
        x[4*q] = v.x; x[4*q+1] = v.y; x[4*q+2] = v.z; x[4*q+3] = v.w;
    }
    float a = __ldg(attr + n) * 0.25f;  // attr / sqrt(16)

    float out[64];
#pragma unroll
    for (int u = 0; u < 16; u++) {
        float acc = 0.f;
#pragma unroll
        for (int v = 0; v < 16; v++) acc += x[v] * w0[u*16 + v];
        out[u] = acc * a;
    }
#pragma unroll
    for (int u = 0; u < 16; u++) {
        float a0 = 0.f, a1 = 0.f, a2 = 0.f;
#pragma unroll
        for (int v = 0; v < 16; v++) {
            float wv = w1[u*16 + v];
            a0 += x[16 + 3*v + 0] * wv;
            a1 += x[16 + 3*v + 1] * wv;
            a2 += x[16 + 3*v + 2] * wv;
        }
        out[16 + 3*u + 0] = a0 * a;
        out[16 + 3*u + 1] = a1 * a;
        out[16 + 3*u + 2] = a2 * a;
    }
    float4* sp = (float4*)(g_s + (size_t)n * 64);
#pragma unroll
    for (int q = 0; q < 16; q++)
        sp[q] = make_float4(out[4*q], out[4*q+1], out[4*q+2], out[4*q+3]);
}

// ======================================================================
// CSR build
// ======================================================================
__global__ void __launch_bounds__(256) hist_kernel(const int* __restrict__ esrc, int E)
{
    int e = blockIdx.x * 256 + threadIdx.x;
    if (e < E) atomicAdd(&g_deg[__ldg(esrc + e)], 1);
}

__global__ void __launch_bounds__(1024) scan_kernel(int N, int E)
{
    __shared__ int part[1024];
    int t = threadIdx.x;
    const int chunk = (MAX_N + 1023) / 1024;   // 49
    int start = t * chunk;
    int end = start + chunk; if (end > N) end = N;
    int s = 0;
    if (start < N) for (int i = start; i < end; i++) s += g_deg[i];
    part[t] = s;
    __syncthreads();
    for (int off = 1; off < 1024; off <<= 1) {
        int v = (t >= off) ? part[t - off] : 0;
        __syncthreads();
        part[t] += v;
        __syncthreads();
    }
    int run = part[t] - s;
    if (start < N) {
        for (int i = start; i < end; i++) {
            g_off[i] = run;
            g_cur[i] = run;
            run += g_deg[i];
        }
    }
    if (t == 0) g_off[N] = E;
}

__global__ void __launch_bounds__(256) scatter_kernel(const int* __restrict__ esrc, int E)
{
    int e = blockIdx.x * 256 + threadIdx.x;
    if (e >= E) return;
    int s = __ldg(esrc + e);
    int p = atomicAdd(&g_cur[s], 1);
    g_eidx[p] = e;
}

// ======================================================================
// Fused edge MLP: per block, 256-edge tile.
//   stage1: dist rows -> smem X[k][e] (transposed, stride 260)
//   phase1: h = silu(x @ W1/8), written back over X in smem
//   phase2: wf = h @ W2/8  -> g_wf (edge order)
// Thread map: 320 threads; phase1 uses t<256 as (q=t&63, p=t>>6, p<4);
//             phase2 uses all 320 as (q=t%64, p=t/64, p<5).
// ======================================================================
__global__ void __launch_bounds__(320) fused_mlp_kernel(
    const float* __restrict__ dist,
    const float* __restrict__ W1, const float* __restrict__ W2, int E)
{
    extern __shared__ float sm[];
    float* sX  = sm;                       // 64 * 260
    float* sW1 = sm + 64 * XSTRIDE;        // 4096
    float* sW2 = sW1 + 4096;               // 5120
    int t = threadIdx.x;

    // load weights, pre-scaled by 1/8
    for (int i = t; i < 1024; i += 320) {
        float4 v = __ldg((const float4*)W1 + i);
        ((float4*)sW1)[i] = make_float4(v.x*0.125f, v.y*0.125f, v.z*0.125f, v.w*0.125f);
    }
    for (int i = t; i < 1280; i += 320) {
        float4 v = __ldg((const float4*)W2 + i);
        ((float4*)sW2)[i] = make_float4(v.x*0.125f, v.y*0.125f, v.z*0.125f, v.w*0.125f);
    }

    int e0 = blockIdx.x * TILE_E;

    // stage 1: coalesced load of dist rows -> transposed smem
    for (int i = t; i < TILE_E * 16; i += 320) {
        int e = i >> 4, seg = i & 15;
        float4 v = make_float4(0.f, 0.f, 0.f, 0.f);
        if (e0 + e < E)
            v = __ldg((const float4*)(dist + (size_t)(e0 + e) * 64) + seg);
        sX[(seg*4 + 0) * XSTRIDE + e] = v.x;
        sX[(seg*4 + 1) * XSTRIDE + e] = v.y;
        sX[(seg*4 + 2) * XSTRIDE + e] = v.z;
        sX[(seg*4 + 3) * XSTRIDE + e] = v.w;
    }
    __syncthreads();

    // ---------------- phase 1 ----------------
    int q1 = t & 63, p1 = t >> 6;
    float h[4][16];
    if (p1 < 4) {
        unsigned long long acc[32];
#pragma unroll
        for (int i = 0; i < 32; i++) acc[i] = 0ULL;
        const float* xcol = sX + 4 * q1;
        const float* wbase = sW1 + p1 * 16;
#pragma unroll 8
        for (int k = 0; k < 64; k++) {
            float4 xv = *(const float4*)(xcol + k * XSTRIDE);
            unsigned long long x0 = pk2s(xv.x), x1 = pk2s(xv.y);
            unsigned long long x2 = pk2s(xv.z), x3 = pk2s(xv.w);
            const ulonglong2* wr = (const ulonglong2*)(wbase + k * 64);
#pragma unroll
            for (int q = 0; q < 4; q++) {
                ulonglong2 w = wr[q];
                ff2(acc[0*8 + 2*q],     x0, w.x);  ff2(acc[0*8 + 2*q + 1], x0, w.y);
                ff2(acc[1*8 + 2*q],     x1, w.x);  ff2(acc[1*8 + 2*q + 1], x1, w.y);
                ff2(acc[2*8 + 2*q],     x2, w.x);  ff2(acc[2*8 + 2*q + 1], x2, w.y);
                ff2(acc[3*8 + 2*q],     x3, w.x);  ff2(acc[3*8 + 2*q + 1], x3, w.y);
            }
        }
#pragma unroll
        for (int j = 0; j < 4; j++)
#pragma unroll
            for (int m = 0; m < 8; m++) {
                float a, b; upk2(acc[j*8 + m], a, b);
                h[j][2*m]   = silu(a);
                h[j][2*m+1] = silu(b);
            }
    }
    __syncthreads();   // everyone done reading X

    // write h over X tile (H[j_out][e], stride 260)
    if (p1 < 4) {
        float* hb = sX + 4 * q1;
#pragma unroll
        for (int o = 0; o < 16; o++)
            *(float4*)(hb + (p1*16 + o) * XSTRIDE) =
                make_float4(h[0][o], h[1][o], h[2][o], h[3][o]);
    }
    __syncthreads();

    // ---------------- phase 2 ----------------
    {
        int q2 = t % 64, p2 = t / 64;      // p2 in 0..4
        unsigned long long acc[32];
#pragma unroll
        for (int i = 0; i < 32; i++) acc[i] = 0ULL;
        const float* hcol = sX + 4 * q2;
        const float* wbase = sW2 + p2 * 16;
#pragma unroll 8
        for (int k = 0; k < 64; k++) {
            float4 hv = *(const float4*)(hcol + k * XSTRIDE);
            unsigned long long x0 = pk2s(hv.x), x1 = pk2s(hv.y);
            unsigned long long x2 = pk2s(hv.z), x3 = pk2s(hv.w);
            const ulonglong2* wr = (const ulonglong2*)(wbase + k * 80);
#pragma unroll
            for (int q = 0; q < 4; q++) {
                ulonglong2 w = wr[q];
                ff2(acc[0*8 + 2*q],     x0, w.x);  ff2(acc[0*8 + 2*q + 1], x0, w.y);
                ff2(acc[1*8 + 2*q],     x1, w.x);  ff2(acc[1*8 + 2*q + 1], x1, w.y);
                ff2(acc[2*8 + 2*q],     x2, w.x);  ff2(acc[2*8 + 2*q + 1], x2, w.y);
                ff2(acc[3*8 + 2*q],     x3, w.x);  ff2(acc[3*8 + 2*q + 1], x3, w.y);
            }
        }
#pragma unroll
        for (int j = 0; j < 4; j++) {
            int e = e0 + 4 * q2 + j;
            if (e < E) {
                ulonglong2* wp = (ulonglong2*)(g_wf + (size_t)e * 80 + p2 * 16);
                ulonglong2 s0; s0.x = acc[j*8+0]; s0.y = acc[j*8+1];
                ulonglong2 s1; s1.x = acc[j*8+2]; s1.y = acc[j*8+3];
                ulonglong2 s2; s2.x = acc[j*8+4]; s2.y = acc[j*8+5];
                ulonglong2 s3; s3.x = acc[j*8+6]; s3.y = acc[j*8+7];
                wp[0] = s0; wp[1] = s1; wp[2] = s2; wp[3] = s3;
            }
        }
    }
}

// ======================================================================
// Aggregation: half-warp (16 lanes) per node, CSR walk via eidx, no atomics
// ======================================================================
__global__ void __launch_bounds__(256) agg_kernel(
    const int* __restrict__ edst, const float* __restrict__ eattr, int N)
{
    int u = threadIdx.x & 15;
    int node = blockIdx.x * 16 + (threadIdx.x >> 4);

    int beg = 0, end = 0;
    if (node < N) { beg = __ldg(&g_off[node]); end = __ldg(&g_off[node + 1]); }

    const float is3 = 0.57735026918962576f;   // 1/sqrt(3)
    const float is2 = 0.70710678118654752f;   // 1/sqrt(2)

    float m0a = 0.f, m0b = 0.f;
    float A0 = 0.f, A1 = 0.f, A2 = 0.f;
    float B0 = 0.f, B1 = 0.f, B2 = 0.f;
    float C0 = 0.f, C1 = 0.f, C2 = 0.f;

    for (int p = beg; p < end; p++) {
        int e = __ldg(g_eidx + p);
        const float* wfp = g_wf + (size_t)e * 80;
        float w0 = __ldg(wfp + u);
        float w1 = __ldg(wfp + 16 + u);
        float w2 = __ldg(wfp + 32 + u);
        float w3 = __ldg(wfp + 48 + u);
        float w4 = __ldg(wfp + 64 + u) * is2;
        int dst = __ldg(edst + e);
        float4 y = __ldg((const float4*)eattr + e);
        const float* gs = g_s + (size_t)dst * 64;
        float g0 = __ldg(gs + u);
        float ga = __ldg(gs + 16 + 3*u);
        float gb = __ldg(gs + 17 + 3*u);
        float gc = __ldg(gs + 18 + 3*u);

        m0a += w0 * g0 * y.x;
        m0b += w3 * (ga*y.y + gb*y.z + gc*y.w) * is3;
        float w1g = w1 * g0;
        A0 += w1g * y.y;  A1 += w1g * y.z;  A2 += w1g * y.w;
        float w2y = w2 * y.x;
        B0 += w2y * ga;   B1 += w2y * gb;   B2 += w2y * gc;
        C0 += w4 * (gb * y.w - gc * y.z);
        C1 += w4 * (gc * y.y - ga * y.w);
        C2 += w4 * (ga * y.z - gb * y.y);
    }

    if (node < N) {
        float* ab = g_agg + (size_t)node * 176;
        ab[u]         = m0a;
        ab[16 + u]    = m0b;
        ab[32 + 3*u]  = A0;  ab[33 + 3*u]  = A1;  ab[34 + 3*u]  = A2;
        ab[80 + 3*u]  = B0;  ab[81 + 3*u]  = B1;  ab[82 + 3*u]  = B2;
        ab[128 + 3*u] = C0;  ab[129 + 3*u] = C1;  ab[130 + 3*u] = C2;
    }
}

// ======================================================================
// Kernel: per-node output: linear-out FCTP * alpha + skip FCTP
// ======================================================================
__global__ void __launch_bounds__(128) node_post_kernel(
    const float* __restrict__ xin, const float* __restrict__ attr,
    const float* __restrict__ Wsc0, const float* __restrict__ Wsc1,
    const float* __restrict__ Wlo0, const float* __restrict__ Wlo1,
    const float* __restrict__ Wal, float* __restrict__ out, int N)
{
    __shared__ float sc0[256], sc1[256], lo0[512], lo1[768], al[32];
    int t = threadIdx.x;
    for (int i = t; i < 256; i += 128) { sc0[i] = Wsc0[i]; sc1[i] = Wsc1[i]; }
    for (int i = t; i < 512; i += 128) lo0[i] = Wlo0[i];
    for (int i = t; i < 768; i += 128) lo1[i] = Wlo1[i];
    if (t < 32) al[t] = Wal[t];
    __syncthreads();

    int n = blockIdx.x * 128 + t;
    if (n >= N) return;

    const float* ag = g_agg + (size_t)n * 176;
    float o0[16], o1[48];
#pragma unroll
    for (int u = 0; u < 16; u++) o0[u] = 0.f;
#pragma unroll
    for (int j = 0; j < 48; j++) o1[j] = 0.f;
    float alpha = 0.f;

#pragma unroll
    for (int vg = 0; vg < 16; vg += 4) {
        float4 P = __ldg((const float4*)(ag + vg));
        float4 Q = __ldg((const float4*)(ag + 16 + vg));
        const float4* Ap = (const float4*)(ag + 32  + 3*vg);
        const float4* Bp = (const float4*)(ag + 80  + 3*vg);
        const float4* Cp = (const float4*)(ag + 128 + 3*vg);
        float4 Af0 = __ldg(Ap), Af1 = __ldg(Ap+1), Af2 = __ldg(Ap+2);
        float4 Bf0 = __ldg(Bp), Bf1 = __ldg(Bp+1), Bf2 = __ldg(Bp+2);
        float4 Cf0 = __ldg(Cp), Cf1 = __ldg(Cp+1), Cf2 = __ldg(Cp+2);
        float m0aq[4] = {P.x, P.y, P.z, P.w};
        float m0bq[4] = {Q.x, Q.y, Q.z, Q.w};
        float Aq[12] = {Af0.x,Af0.y,Af0.z,Af0.w,Af1.x,Af1.y,Af1.z,Af1.w,Af2.x,Af2.y,Af2.z,Af2.w};
        float Bq[12] = {Bf0.x,Bf0.y,Bf0.z,Bf0.w,Bf1.x,Bf1.y,Bf1.z,Bf1.w,Bf2.x,Bf2.y,Bf2.z,Bf2.w};
        float Cq[12] = {Cf0.x,Cf0.y,Cf0.z,Cf0.w,Cf1.x,Cf1.y,Cf1.z,Cf1.w,Cf2.x,Cf2.y,Cf2.z,Cf2.w};
#pragma unroll
        for (int j = 0; j < 4; j++) {
            int v = vg + j;
            float m0a = m0aq[j] * 0.25f;   // / sqrt(NUM_NEIGHBORS)
            float m0b = m0bq[j] * 0.25f;
            float Ax = Aq[3*j]*0.25f, Ay = Aq[3*j+1]*0.25f, Az = Aq[3*j+2]*0.25f;
            float Bx = Bq[3*j]*0.25f, By = Bq[3*j+1]*0.25f, Bz = Bq[3*j+2]*0.25f;
            float Cx = Cq[3*j]*0.25f, Cy = Cq[3*j+1]*0.25f, Cz = Cq[3*j+2]*0.25f;
            alpha += m0a * al[v] + m0b * al[16 + v];
#pragma unroll
            for (int u = 0; u < 16; u++) {
                o0[u] += m0a * lo0[u*32 + v] + m0b * lo0[u*32 + 16 + v];
                float wa = lo1[u*48 + v], wb = lo1[u*48 + 16 + v], wc = lo1[u*48 + 32 + v];
                o1[u*3 + 0] += Ax * wa + Bx * wb + Cx * wc;
                o1[u*3 + 1] += Ay * wa + By * wb + Cy * wc;
                o1[u*3 + 2] += Az * wa + Bz * wb + Cz * wc;
            }
        }
    }

    float x[64];
    const float4* xp = (const float4*)(xin + (size_t)n * 64);
#pragma unroll
    for (int q = 0; q < 16; q++) {
        float4 v4 = __ldg(xp + q);
        x[4*q] = v4.x; x[4*q+1] = v4.y; x[4*q+2] = v4.z; x[4*q+3] = v4.w;
    }
    float a   = __ldg(attr + n);
    float a4  = a * 0.25f;
    float s32 = a * 0.17677669529663689f;
    float s48 = a * 0.14433756729740643f;
    float alphaf = alpha * s32;

    float res[64];
#pragma unroll
    for (int u = 0; u < 16; u++) {
        float sk = 0.f;
#pragma unroll
        for (int v = 0; v < 16; v++) sk += x[v] * sc0[u*16 + v];
        res[u] = o0[u] * s32 * alphaf + sk * a4;
    }
#pragma unroll
    for (int u = 0; u < 16; u++) {
        float sa = 0.f, sb = 0.f, sc = 0.f;
#pragma unroll
        for (int v = 0; v < 16; v++) {
            float wv = sc1[u*16 + v];
            sa += x[16 + 3*v + 0] * wv;
            sb += x[16 + 3*v + 1] * wv;
            sc += x[16 + 3*v + 2] * wv;
        }
        res[16 + 3*u + 0] = o1[3*u + 0] * s48 * alphaf + sa * a4;
        res[16 + 3*u + 1] = o1[3*u + 1] * s48 * alphaf + sb * a4;
        res[16 + 3*u + 2] = o1[3*u + 2] * s48 * alphaf + sc * a4;
    }
    float4* op = (float4*)(out + (size_t)n * 64);
#pragma unroll
    for (int q = 0; q < 16; q++)
        op[q] = make_float4(res[4*q], res[4*q+1], res[4*q+2], res[4*q+3]);
}

// ======================================================================
extern "C" void kernel_launch(void* const* d_in, const int* in_sizes, int n_in,
                              void* d_out, int out_size)
{
    const float* node_input = (const float*)d_in[0];
    const float* node_attr  = (const float*)d_in[1];
    const int*   esrc       = (const int*)d_in[2];
    const int*   edst       = (const int*)d_in[3];
    const float* eattr      = (const float*)d_in[4];
    const float* dist       = (const float*)d_in[5];
    const float* Wsi0 = (const float*)d_in[6];
    const float* Wsi1 = (const float*)d_in[7];
    const float* Wsc0 = (const float*)d_in[8];
    const float* Wsc1 = (const float*)d_in[9];
    const float* Wm1  = (const float*)d_in[10];
    const float* Wm2  = (const float*)d_in[11];
    const float* Wlo0 = (const float*)d_in[12];
    const float* Wlo1 = (const float*)d_in[13];
    const float* Wal  = (const float*)d_in[14];

    int N = in_sizes[0] / 64;
    int E = in_sizes[2];

    int smem_bytes = (64 * XSTRIDE + 4096 + 5120) * (int)sizeof(float);  // 103424
    cudaFuncSetAttribute(fused_mlp_kernel, cudaFuncAttributeMaxDynamicSharedMemorySize, smem_bytes);

    node_pre_kernel<<<(N + 127) / 128, 128>>>(node_input, node_attr, Wsi0, Wsi1, N); // 0
    hist_kernel<<<(E + 255) / 256, 256>>>(esrc, E);                                  // 1
    scan_kernel<<<1, 1024>>>(N, E);                                                  // 2
    fused_mlp_kernel<<<(E + TILE_E - 1) / TILE_E, 320, smem_bytes>>>(dist, Wm1, Wm2, E); // 3 (profiled)
    scatter_kernel<<<(E + 255) / 256, 256>>>(esrc, E);                               // 4
    agg_kernel<<<(N + 15) / 16, 256>>>(edst, eattr, N);                              // 5
    node_post_kernel<<<(N + 127) / 128, 128>>>(node_input, node_attr, Wsc0, Wsc1,
                                               Wlo0, Wlo1, Wal, (float*)d_out, N);   // 6
}

// round 6
// speedup vs baseline: 1.0798x; 1.0798x over previous
#include <cuda_runtime.h>
#include <cstdint>
#include <cstddef>

#define MAX_N 50000
#define MAX_E 800000
#define TILE_E 256
#define XSTRIDE 260   // floats; 260*4=1040B, 16B-aligned rows, bank-shift 4/row

// Scratch (static device globals — no runtime allocation)
__device__ float g_s[MAX_N * 64];            // per-node s0(16) + s1(16x3)
__device__ float g_agg[MAX_N * 176];         // m0a16|m0b16|m1a48|m1b48|m1c48
__device__ float g_wf[(size_t)MAX_E * 80];   // per-edge MLP out, CSR-permuted rows
__device__ float g_yp[(size_t)MAX_E * 4];    // eattr, CSR-permuted
__device__ int   g_dstp[MAX_E];              // edge dst, CSR-permuted
__device__ int   g_pos[MAX_E];               // edge -> CSR slot
__device__ int   g_deg[MAX_N];
__device__ int   g_off[MAX_N + 1];
__device__ int   g_cur[MAX_N];

// ---------- packed fp32x2 helpers (sm_103a) ----------
__device__ __forceinline__ unsigned long long pk2s(float a) {
    unsigned long long r;
    asm("mov.b64 %0, {%1,%1};" : "=l"(r) : "f"(a));
    return r;
}
__device__ __forceinline__ void upk2(unsigned long long v, float& a, float& b) {
    asm("mov.b64 {%0,%1}, %2;" : "=f"(a), "=f"(b) : "l"(v));
}
__device__ __forceinline__ void ff2(unsigned long long& d, unsigned long long a, unsigned long long b) {
    asm("fma.rn.f32x2 %0, %1, %2, %0;" : "+l"(d) : "l"(a), "l"(b));
}
__device__ __forceinline__ float silu(float v) {
    return v / (1.f + __expf(-v));
}

// ======================================================================
// Kernel: self-interaction s = FCTP(x, attr; W_si)  + zero degree array
// ======================================================================
__global__ void __launch_bounds__(128) node_pre_kernel(
    const float* __restrict__ xin, const float* __restrict__ attr,
    const float* __restrict__ Wsi0, const float* __restrict__ Wsi1, int N)
{
    __shared__ float w0[256], w1[256];
    int t = threadIdx.x;
    if (t < 128) { w0[t] = Wsi0[t]; w0[t + 128] = Wsi0[t + 128];
                   w1[t] = Wsi1[t]; w1[t + 128] = Wsi1[t + 128]; }
    __syncthreads();
    int n = blockIdx.x * 128 + t;
    if (n >= N) return;

    g_deg[n] = 0;

    float x[64];
    const float4* xp = (const float4*)(xin + (size_t)n * 64);
#pragma unroll
    for (int q = 0; q < 16; q++) {
        float4 v = __ldg(xp + q);
        x[4*q] = v.x; x[4*q+1] = v.y; x[4*q+2] = v.z; x[4*q+3] = v.w;
    }
    float a = __ldg(attr + n) * 0.25f;  // attr / sqrt(16)

    float out[64];
#pragma unroll
    for (int u = 0; u < 16; u++) {
        float acc = 0.f;
#pragma unroll
        for (int v = 0; v < 16; v++) acc += x[v] * w0[u*16 + v];
        out[u] = acc * a;
    }
#pragma unroll
    for (int u = 0; u < 16; u++) {
        float a0 = 0.f, a1 = 0.f, a2 = 0.f;
#pragma unroll
        for (int v = 0; v < 16; v++) {
            float wv = w1[u*16 + v];
            a0 += x[16 + 3*v + 0] * wv;
            a1 += x[16 + 3*v + 1] * wv;
            a2 += x[16 + 3*v + 2] * wv;
        }
        out[16 + 3*u + 0] = a0 * a;
        out[16 + 3*u + 1] = a1 * a;
        out[16 + 3*u + 2] = a2 * a;
    }
    float4* sp = (float4*)(g_s + (size_t)n * 64);
#pragma unroll
    for (int q = 0; q < 16; q++)
        sp[q] = make_float4(out[4*q], out[4*q+1], out[4*q+2], out[4*q+3]);
}

// ======================================================================
// CSR build
// ======================================================================
__global__ void __launch_bounds__(256) hist_kernel(const int* __restrict__ esrc, int E)
{
    int e = blockIdx.x * 256 + threadIdx.x;
    if (e < E) atomicAdd(&g_deg[__ldg(esrc + e)], 1);
}

__global__ void __launch_bounds__(1024) scan_kernel(int N, int E)
{
    __shared__ int part[1024];
    int t = threadIdx.x;
    const int chunk = (MAX_N + 1023) / 1024;   // 49
    int start = t * chunk;
    int end = start + chunk; if (end > N) end = N;
    int s = 0;
    if (start < N) for (int i = start; i < end; i++) s += g_deg[i];
    part[t] = s;
    __syncthreads();
    for (int off = 1; off < 1024; off <<= 1) {
        int v = (t >= off) ? part[t - off] : 0;
        __syncthreads();
        part[t] += v;
        __syncthreads();
    }
    int run = part[t] - s;
    if (start < N) {
        for (int i = start; i < end; i++) {
            g_off[i] = run;
            g_cur[i] = run;
            run += g_deg[i];
        }
    }
    if (t == 0) g_off[N] = E;
}

__global__ void __launch_bounds__(256) scatter_kernel(
    const int* __restrict__ esrc, const int* __restrict__ edst,
    const float* __restrict__ eattr, int E)
{
    int e = blockIdx.x * 256 + threadIdx.x;
    if (e >= E) return;
    int s = __ldg(esrc + e);
    int p = atomicAdd(&g_cur[s], 1);
    g_pos[e] = p;
    g_dstp[p] = __ldg(edst + e);
    float4 y = __ldg((const float4*)eattr + e);
    *((float4*)g_yp + p) = y;
}

// ======================================================================
// Fused edge MLP: per block, 256-edge tile.
//   stage1: dist rows -> smem X[k][e] (transposed, stride 260)
//   phase1: h = silu(x @ W1/8), written back over X in smem
//   phase2: wf = h @ W2/8  -> g_wf rows at CSR slot pos[e]
// 320 threads, forced 2 blocks/SM (regfile was capping occupancy at 1 block).
// ======================================================================
__global__ void __launch_bounds__(320, 2) fused_mlp_kernel(
    const float* __restrict__ dist,
    const float* __restrict__ W1, const float* __restrict__ W2, int E)
{
    extern __shared__ float sm[];
    float* sX  = sm;                       // 64 * 260
    float* sW1 = sm + 64 * XSTRIDE;        // 4096
    float* sW2 = sW1 + 4096;               // 5120
    int t = threadIdx.x;

    // load weights, pre-scaled by 1/8
    for (int i = t; i < 1024; i += 320) {
        float4 v = __ldg((const float4*)W1 + i);
        ((float4*)sW1)[i] = make_float4(v.x*0.125f, v.y*0.125f, v.z*0.125f, v.w*0.125f);
    }
    for (int i = t; i < 1280; i += 320) {
        float4 v = __ldg((const float4*)W2 + i);
        ((float4*)sW2)[i] = make_float4(v.x*0.125f, v.y*0.125f, v.z*0.125f, v.w*0.125f);
    }

    int e0 = blockIdx.x * TILE_E;

    // stage 1: coalesced load of dist rows -> transposed smem
    for (int i = t; i < TILE_E * 16; i += 320) {
        int e = i >> 4, seg = i & 15;
        float4 v = make_float4(0.f, 0.f, 0.f, 0.f);
        if (e0 + e < E)
            v = __ldg((const float4*)(dist + (size_t)(e0 + e) * 64) + seg);
        sX[(seg*4 + 0) * XSTRIDE + e] = v.x;
        sX[(seg*4 + 1) * XSTRIDE + e] = v.y;
        sX[(seg*4 + 2) * XSTRIDE + e] = v.z;
        sX[(seg*4 + 3) * XSTRIDE + e] = v.w;
    }
    __syncthreads();

    // ---------------- phase 1 ----------------
    int q1 = t & 63, p1 = t >> 6;
    float h[4][16];
    if (p1 < 4) {
        unsigned long long acc[32];
#pragma unroll
        for (int i = 0; i < 32; i++) acc[i] = 0ULL;
        const float* xcol = sX + 4 * q1;
        const float* wbase = sW1 + p1 * 16;
#pragma unroll 8
        for (int k = 0; k < 64; k++) {
            float4 xv = *(const float4*)(xcol + k * XSTRIDE);
            unsigned long long x0 = pk2s(xv.x), x1 = pk2s(xv.y);
            unsigned long long x2 = pk2s(xv.z), x3 = pk2s(xv.w);
            const ulonglong2* wr = (const ulonglong2*)(wbase + k * 64);
#pragma unroll
            for (int q = 0; q < 4; q++) {
                ulonglong2 w = wr[q];
                ff2(acc[0*8 + 2*q],     x0, w.x);  ff2(acc[0*8 + 2*q + 1], x0, w.y);
                ff2(acc[1*8 + 2*q],     x1, w.x);  ff2(acc[1*8 + 2*q + 1], x1, w.y);
                ff2(acc[2*8 + 2*q],     x2, w.x);  ff2(acc[2*8 + 2*q + 1], x2, w.y);
                ff2(acc[3*8 + 2*q],     x3, w.x);  ff2(acc[3*8 + 2*q + 1], x3, w.y);
            }
        }
#pragma unroll
        for (int j = 0; j < 4; j++)
#pragma unroll
            for (int m = 0; m < 8; m++) {
                float a, b; upk2(acc[j*8 + m], a, b);
                h[j][2*m]   = silu(a);
                h[j][2*m+1] = silu(b);
            }
    }
    __syncthreads();   // everyone done reading X

    // write h over X tile (H[j_out][e], stride 260)
    if (p1 < 4) {
        float* hb = sX + 4 * q1;
#pragma unroll
        for (int o = 0; o < 16; o++)
            *(float4*)(hb + (p1*16 + o) * XSTRIDE) =
                make_float4(h[0][o], h[1][o], h[2][o], h[3][o]);
    }
    __syncthreads();

    // ---------------- phase 2 ----------------
    {
        int q2 = t % 64, p2 = t / 64;      // p2 in 0..4
        int ebase = e0 + 4 * q2;
        int pos[4];
        if (ebase + 3 < E) {
            int4 pv = *(const int4*)(g_pos + ebase);
            pos[0] = pv.x; pos[1] = pv.y; pos[2] = pv.z; pos[3] = pv.w;
        } else {
#pragma unroll
            for (int j = 0; j < 4; j++)
                pos[j] = (ebase + j < E) ? g_pos[ebase + j] : 0;
        }

        unsigned long long acc[32];
#pragma unroll
        for (int i = 0; i < 32; i++) acc[i] = 0ULL;
        const float* hcol = sX + 4 * q2;
        const float* wbase = sW2 + p2 * 16;
#pragma unroll 8
        for (int k = 0; k < 64; k++) {
            float4 hv = *(const float4*)(hcol + k * XSTRIDE);
            unsigned long long x0 = pk2s(hv.x), x1 = pk2s(hv.y);
            unsigned long long x2 = pk2s(hv.z), x3 = pk2s(hv.w);
            const ulonglong2* wr = (const ulonglong2*)(wbase + k * 80);
#pragma unroll
            for (int q = 0; q < 4; q++) {
                ulonglong2 w = wr[q];
                ff2(acc[0*8 + 2*q],     x0, w.x);  ff2(acc[0*8 + 2*q + 1], x0, w.y);
                ff2(acc[1*8 + 2*q],     x1, w.x);  ff2(acc[1*8 + 2*q + 1], x1, w.y);
                ff2(acc[2*8 + 2*q],     x2, w.x);  ff2(acc[2*8 + 2*q + 1], x2, w.y);
                ff2(acc[3*8 + 2*q],     x3, w.x);  ff2(acc[3*8 + 2*q + 1], x3, w.y);
            }
        }
#pragma unroll
        for (int j = 0; j < 4; j++) {
            if (ebase + j < E) {
                ulonglong2* wp = (ulonglong2*)(g_wf + (size_t)pos[j] * 80 + p2 * 16);
                ulonglong2 s0; s0.x = acc[j*8+0]; s0.y = acc[j*8+1];
                ulonglong2 s1; s1.x = acc[j*8+2]; s1.y = acc[j*8+3];
                ulonglong2 s2; s2.x = acc[j*8+4]; s2.y = acc[j*8+5];
                ulonglong2 s3; s3.x = acc[j*8+6]; s3.y = acc[j*8+7];
                wp[0] = s0; wp[1] = s1; wp[2] = s2; wp[3] = s3;
            }
        }
    }
}

// ======================================================================
// Aggregation: half-warp (16 lanes) per node, fully sequential CSR walk
// ======================================================================
__global__ void __launch_bounds__(256) agg_kernel(int N)
{
    int u = threadIdx.x & 15;
    int node = blockIdx.x * 16 + (threadIdx.x >> 4);

    int beg = 0, end = 0;
    if (node < N) { beg = __ldg(&g_off[node]); end = __ldg(&g_off[node + 1]); }

    const float is3 = 0.57735026918962576f;   // 1/sqrt(3)
    const float is2 = 0.70710678118654752f;   // 1/sqrt(2)

    float m0a = 0.f, m0b = 0.f;
    float A0 = 0.f, A1 = 0.f, A2 = 0.f;
    float B0 = 0.f, B1 = 0.f, B2 = 0.f;
    float C0 = 0.f, C1 = 0.f, C2 = 0.f;

    for (int p = beg; p < end; p++) {
        const float* wfp = g_wf + (size_t)p * 80;
        float w0 = __ldg(wfp + u);
        float w1 = __ldg(wfp + 16 + u);
        float w2 = __ldg(wfp + 32 + u);
        float w3 = __ldg(wfp + 48 + u);
        float w4 = __ldg(wfp + 64 + u) * is2;
        int dst = __ldg(g_dstp + p);
        float4 y = __ldg((const float4*)g_yp + p);
        const float* gs = g_s + (size_t)dst * 64;
        float g0 = __ldg(gs + u);
        float ga = __ldg(gs + 16 + 3*u);
        float gb = __ldg(gs + 17 + 3*u);
        float gc = __ldg(gs + 18 + 3*u);

        m0a += w0 * g0 * y.x;
        m0b += w3 * (ga*y.y + gb*y.z + gc*y.w) * is3;
        float w1g = w1 * g0;
        A0 += w1g * y.y;  A1 += w1g * y.z;  A2 += w1g * y.w;
        float w2y = w2 * y.x;
        B0 += w2y * ga;   B1 += w2y * gb;   B2 += w2y * gc;
        C0 += w4 * (gb * y.w - gc * y.z);
        C1 += w4 * (gc * y.y - ga * y.w);
        C2 += w4 * (ga * y.z - gb * y.y);
    }

    if (node < N) {
        float* ab = g_agg + (size_t)node * 176;
        ab[u]         = m0a;
        ab[16 + u]    = m0b;
        ab[32 + 3*u]  = A0;  ab[33 + 3*u]  = A1;  ab[34 + 3*u]  = A2;
        ab[80 + 3*u]  = B0;  ab[81 + 3*u]  = B1;  ab[82 + 3*u]  = B2;
        ab[128 + 3*u] = C0;  ab[129 + 3*u] = C1;  ab[130 + 3*u] = C2;
    }
}

// ======================================================================
// Kernel: per-node output: linear-out FCTP * alpha + skip FCTP
// ======================================================================
__global__ void __launch_bounds__(128) node_post_kernel(
    const float* __restrict__ xin, const float* __restrict__ attr,
    const float* __restrict__ Wsc0, const float* __restrict__ Wsc1,
    const float* __restrict__ Wlo0, const float* __restrict__ Wlo1,
    const float* __restrict__ Wal, float* __restrict__ out, int N)
{
    __shared__ float sc0[256], sc1[256], lo0[512], lo1[768], al[32];
    int t = threadIdx.x;
    for (int i = t; i < 256; i += 128) { sc0[i] = Wsc0[i]; sc1[i] = Wsc1[i]; }
    for (int i = t; i < 512; i += 128) lo0[i] = Wlo0[i];
    for (int i = t; i < 768; i += 128) lo1[i] = Wlo1[i];
    if (t < 32) al[t] = Wal[t];
    __syncthreads();

    int n = blockIdx.x * 128 + t;
    if (n >= N) return;

    const float* ag = g_agg + (size_t)n * 176;
    float o0[16], o1[48];
#pragma unroll
    for (int u = 0; u < 16; u++) o0[u] = 0.f;
#pragma unroll
    for (int j = 0; j < 48; j++) o1[j] = 0.f;
    float alpha = 0.f;

#pragma unroll
    for (int vg = 0; vg < 16; vg += 4) {
        float4 P = __ldg((const float4*)(ag + vg));
        float4 Q = __ldg((const float4*)(ag + 16 + vg));
        const float4* Ap = (const float4*)(ag + 32  + 3*vg);
        const float4* Bp = (const float4*)(ag + 80  + 3*vg);
        const float4* Cp = (const float4*)(ag + 128 + 3*vg);
        float4 Af0 = __ldg(Ap), Af1 = __ldg(Ap+1), Af2 = __ldg(Ap+2);
        float4 Bf0 = __ldg(Bp), Bf1 = __ldg(Bp+1), Bf2 = __ldg(Bp+2);
        float4 Cf0 = __ldg(Cp), Cf1 = __ldg(Cp+1), Cf2 = __ldg(Cp+2);
        float m0aq[4] = {P.x, P.y, P.z, P.w};
        float m0bq[4] = {Q.x, Q.y, Q.z, Q.w};
        float Aq[12] = {Af0.x,Af0.y,Af0.z,Af0.w,Af1.x,Af1.y,Af1.z,Af1.w,Af2.x,Af2.y,Af2.z,Af2.w};
        float Bq[12] = {Bf0.x,Bf0.y,Bf0.z,Bf0.w,Bf1.x,Bf1.y,Bf1.z,Bf1.w,Bf2.x,Bf2.y,Bf2.z,Bf2.w};
        float Cq[12] = {Cf0.x,Cf0.y,Cf0.z,Cf0.w,Cf1.x,Cf1.y,Cf1.z,Cf1.w,Cf2.x,Cf2.y,Cf2.z,Cf2.w};
#pragma unroll
        for (int j = 0; j < 4; j++) {
            int v = vg + j;
            float m0a = m0aq[j] * 0.25f;   // / sqrt(NUM_NEIGHBORS)
            float m0b = m0bq[j] * 0.25f;
            float Ax = Aq[3*j]*0.25f, Ay = Aq[3*j+1]*0.25f, Az = Aq[3*j+2]*0.25f;
            float Bx = Bq[3*j]*0.25f, By = Bq[3*j+1]*0.25f, Bz = Bq[3*j+2]*0.25f;
            float Cx = Cq[3*j]*0.25f, Cy = Cq[3*j+1]*0.25f, Cz = Cq[3*j+2]*0.25f;
            alpha += m0a * al[v] + m0b * al[16 + v];
#pragma unroll
            for (int u = 0; u < 16; u++) {
                o0[u] += m0a * lo0[u*32 + v] + m0b * lo0[u*32 + 16 + v];
                float wa = lo1[u*48 + v], wb = lo1[u*48 + 16 + v], wc = lo1[u*48 + 32 + v];
                o1[u*3 + 0] += Ax * wa + Bx * wb + Cx * wc;
                o1[u*3 + 1] += Ay * wa + By * wb + Cy * wc;
                o1[u*3 + 2] += Az * wa + Bz * wb + Cz * wc;
            }
        }
    }

    float x[64];
    const float4* xp = (const float4*)(xin + (size_t)n * 64);
#pragma unroll
    for (int q = 0; q < 16; q++) {
        float4 v4 = __ldg(xp + q);
        x[4*q] = v4.x; x[4*q+1] = v4.y; x[4*q+2] = v4.z; x[4*q+3] = v4.w;
    }
    float a   = __ldg(attr + n);
    float a4  = a * 0.25f;
    float s32 = a * 0.17677669529663689f;
    float s48 = a * 0.14433756729740643f;
    float alphaf = alpha * s32;

    float res[64];
#pragma unroll
    for (int u = 0; u < 16; u++) {
        float sk = 0.f;
#pragma unroll
        for (int v = 0; v < 16; v++) sk += x[v] * sc0[u*16 + v];
        res[u] = o0[u] * s32 * alphaf + sk * a4;
    }
#pragma unroll
    for (int u = 0; u < 16; u++) {
        float sa = 0.f, sb = 0.f, sc = 0.f;
#pragma unroll
        for (int v = 0; v < 16; v++) {
            float wv = sc1[u*16 + v];
            sa += x[16 + 3*v + 0] * wv;
            sb += x[16 + 3*v + 1] * wv;
            sc += x[16 + 3*v + 2] * wv;
        }
        res[16 + 3*u + 0] = o1[3*u + 0] * s48 * alphaf + sa * a4;
        res[16 + 3*u + 1] = o1[3*u + 1] * s48 * alphaf + sb * a4;
        res[16 + 3*u + 2] = o1[3*u + 2] * s48 * alphaf + sc * a4;
    }
    float4* op = (float4*)(out + (size_t)n * 64);
#pragma unroll
    for (int q = 0; q < 16; q++)
        op[q] = make_float4(res[4*q], res[4*q+1], res[4*q+2], res[4*q+3]);
}

// ======================================================================
extern "C" void kernel_launch(void* const* d_in, const int* in_sizes, int n_in,
                              void* d_out, int out_size)
{
    const float* node_input = (const float*)d_in[0];
    const float* node_attr  = (const float*)d_in[1];
    const int*   esrc       = (const int*)d_in[2];
    const int*   edst       = (const int*)d_in[3];
    const float* eattr      = (const float*)d_in[4];
    const float* dist       = (const float*)d_in[5];
    const float* Wsi0 = (const float*)d_in[6];
    const float* Wsi1 = (const float*)d_in[7];
    const float* Wsc0 = (const float*)d_in[8];
    const float* Wsc1 = (const float*)d_in[9];
    const float* Wm1  = (const float*)d_in[10];
    const float* Wm2  = (const float*)d_in[11];
    const float* Wlo0 = (const float*)d_in[12];
    const float* Wlo1 = (const float*)d_in[13];
    const float* Wal  = (const float*)d_in[14];

    int N = in_sizes[0] / 64;
    int E = in_sizes[2];

    int smem_bytes = (64 * XSTRIDE + 4096 + 5120) * (int)sizeof(float);  // 103424
    cudaFuncSetAttribute(fused_mlp_kernel, cudaFuncAttributeMaxDynamicSharedMemorySize, smem_bytes);

    node_pre_kernel<<<(N + 127) / 128, 128>>>(node_input, node_attr, Wsi0, Wsi1, N);  // 0
    hist_kernel<<<(E + 255) / 256, 256>>>(esrc, E);                                   // 1
    scan_kernel<<<1, 1024>>>(N, E);                                                   // 2
    scatter_kernel<<<(E + 255) / 256, 256>>>(esrc, edst, eattr, E);                   // 3 (profiled)
    fused_mlp_kernel<<<(E + TILE_E - 1) / TILE_E, 320, smem_bytes>>>(dist, Wm1, Wm2, E); // 4
    agg_kernel<<<(N + 15) / 16, 256>>>(N);                                            // 5
    node_post_kernel<<<(N + 127) / 128, 128>>>(node_input, node_attr, Wsc0, Wsc1,
                                               Wlo0, Wlo1, Wal, (float*)d_out, N);    // 6
}

// round 7
// speedup vs baseline: 1.2936x; 1.1981x over previous
#include <cuda_runtime.h>
#include <cstdint>
#include <cstddef>

#define MAX_N 50000
#define MAX_E 800000
#define TILE_E 256
#define XSTRIDE 260   // floats; 260*4=1040B rows, 16B-aligned, 4-float bank shift

// Scratch (static device globals — no runtime allocation; zero-initialized)
__device__ float g_s[MAX_N * 64];            // per-node s0(16) + s1(16x3)
__device__ float g_agg[MAX_N * 176];         // m0a16|m0b16|m1a48|m1b48|m1c48
__device__ float g_wf[(size_t)MAX_E * 80];   // per-edge MLP out, CSR-permuted rows
__device__ float g_yp[(size_t)MAX_E * 4];    // eattr, CSR-permuted
__device__ int   g_dstp[MAX_E];              // edge dst, CSR-permuted
__device__ int   g_pos[MAX_E];               // edge -> CSR slot
__device__ int   g_deg[MAX_N];               // zeroed at end of each call
__device__ int   g_off[MAX_N + 1];
__device__ int   g_cur[MAX_N];

// ---------- packed fp32x2 helpers (sm_103a) ----------
__device__ __forceinline__ unsigned long long pk2s(float a) {
    unsigned long long r;
    asm("mov.b64 %0, {%1,%1};" : "=l"(r) : "f"(a));
    return r;
}
__device__ __forceinline__ void upk2(unsigned long long v, float& a, float& b) {
    asm("mov.b64 {%0,%1}, %2;" : "=f"(a), "=f"(b) : "l"(v));
}
__device__ __forceinline__ void ff2(unsigned long long& d, unsigned long long a, unsigned long long b) {
    asm("fma.rn.f32x2 %0, %1, %2, %0;" : "+l"(d) : "l"(a), "l"(b));
}
__device__ __forceinline__ float silu(float v) {
    return v / (1.f + __expf(-v));
}

// ======================================================================
// CSR build
// ======================================================================
__global__ void __launch_bounds__(256) hist_kernel(const int* __restrict__ esrc, int E)
{
    int e = blockIdx.x * 256 + threadIdx.x;
    if (e < E) atomicAdd(&g_deg[__ldg(esrc + e)], 1);
}

__global__ void __launch_bounds__(1024) scan_kernel(int N, int E)
{
    __shared__ int part[1024];
    int t = threadIdx.x;
    const int chunk = (MAX_N + 1023) / 1024;   // 49
    int start = t * chunk;
    int end = start + chunk; if (end > N) end = N;
    int s = 0;
    if (start < N) for (int i = start; i < end; i++) s += g_deg[i];
    part[t] = s;
    __syncthreads();
    for (int off = 1; off < 1024; off <<= 1) {
        int v = (t >= off) ? part[t - off] : 0;
        __syncthreads();
        part[t] += v;
        __syncthreads();
    }
    int run = part[t] - s;
    if (start < N) {
        for (int i = start; i < end; i++) {
            g_off[i] = run;
            g_cur[i] = run;
            run += g_deg[i];
        }
    }
    if (t == 0) g_off[N] = E;
}

__global__ void __launch_bounds__(256) scatter_kernel(
    const int* __restrict__ esrc, const int* __restrict__ edst,
    const float* __restrict__ eattr, int E)
{
    int e = blockIdx.x * 256 + threadIdx.x;
    if (e >= E) return;
    int s = __ldg(esrc + e);
    int p = atomicAdd(&g_cur[s], 1);
    g_pos[e] = p;
    g_dstp[p] = __ldg(edst + e);
    float4 y = __ldg((const float4*)eattr + e);
    *((float4*)g_yp + p) = y;
}

// ======================================================================
// Fused edge MLP: 256-edge tile, 256 threads, 2 edges/thread, half-tile passes.
//   Per-thread activation columns are PRIVATE -> no syncs inside phases.
//   phase1 (q=t&63, p=t>>6): outputs 16p..16p+15 for edges {2q, 2q+1} of half
//   phase2 (q=t&63, p=t>>6): outputs 20p..20p+19
// ======================================================================
__global__ void __launch_bounds__(256) fused_mlp_kernel(
    const float* __restrict__ dist,
    const float* __restrict__ W1, const float* __restrict__ W2, int E)
{
    extern __shared__ float sm[];
    float* sX  = sm;                       // 64 * 260
    float* sW1 = sm + 64 * XSTRIDE;        // 4096
    float* sW2 = sW1 + 4096;               // 5120
    int t = threadIdx.x;

    // load weights, pre-scaled by 1/8
    for (int i = t; i < 1024; i += 256) {
        float4 v = __ldg((const float4*)W1 + i);
        ((float4*)sW1)[i] = make_float4(v.x*0.125f, v.y*0.125f, v.z*0.125f, v.w*0.125f);
    }
    for (int i = t; i < 1280; i += 256) {
        float4 v = __ldg((const float4*)W2 + i);
        ((float4*)sW2)[i] = make_float4(v.x*0.125f, v.y*0.125f, v.z*0.125f, v.w*0.125f);
    }

    int e0 = blockIdx.x * TILE_E;

    // stage: coalesced load of dist rows -> transposed smem X[k][e]
    for (int i = t; i < TILE_E * 16; i += 256) {
        int e = i >> 4, seg = i & 15;
        float4 v = make_float4(0.f, 0.f, 0.f, 0.f);
        if (e0 + e < E)
            v = __ldg((const float4*)(dist + (size_t)(e0 + e) * 64) + seg);
        sX[(seg*4 + 0) * XSTRIDE + e] = v.x;
        sX[(seg*4 + 1) * XSTRIDE + e] = v.y;
        sX[(seg*4 + 2) * XSTRIDE + e] = v.z;
        sX[(seg*4 + 3) * XSTRIDE + e] = v.w;
    }
    __syncthreads();

    int q = t & 63, p = t >> 6;   // p in 0..3

    // ---------------- phase 1: h = silu(x @ W1/8), in-place over X ----------------
#pragma unroll
    for (int half = 0; half < 2; half++) {
        int col = half * 128 + 2 * q;            // this thread's 2 private columns
        unsigned long long acc[16];              // 2 edges x 8 u64 (16 outputs)
#pragma unroll
        for (int i = 0; i < 16; i++) acc[i] = 0ULL;
        const float* xcol = sX + col;
        const float* wbase = sW1 + p * 16;
#pragma unroll 4
        for (int k = 0; k < 64; k++) {
            float2 xv = *(const float2*)(xcol + k * XSTRIDE);
            unsigned long long x0 = pk2s(xv.x), x1 = pk2s(xv.y);
            const ulonglong2* wr = (const ulonglong2*)(wbase + k * 64);
#pragma unroll
            for (int m = 0; m < 4; m++) {
                ulonglong2 w = wr[m];
                ff2(acc[2*m],     x0, w.x);  ff2(acc[2*m + 1],     x0, w.y);
                ff2(acc[8 + 2*m], x1, w.x);  ff2(acc[8 + 2*m + 1], x1, w.y);
            }
        }
        // silu + write h back over X rows [16p,16p+16) for these 2 cols
        float* hb = sX + col;
#pragma unroll
        for (int m = 0; m < 8; m++) {
            float a0, b0, a1, b1;
            upk2(acc[m],     a0, b0);
            upk2(acc[8 + m], a1, b1);
            int r0 = p*16 + 2*m, r1 = r0 + 1;
            *(float2*)(hb + r0 * XSTRIDE) = make_float2(silu(a0), silu(a1));
            *(float2*)(hb + r1 * XSTRIDE) = make_float2(silu(b0), silu(b1));
        }
    }
    __syncthreads();   // phase2 reads rows written by other p-groups

    // ---------------- phase 2: wf = h @ W2/8 -> g_wf at CSR slot ----------------
#pragma unroll
    for (int half = 0; half < 2; half++) {
        int col = half * 128 + 2 * q;
        int ebase = e0 + col;
        int pos0 = (ebase     < E) ? __ldg(g_pos + ebase)     : 0;
        int pos1 = (ebase + 1 < E) ? __ldg(g_pos + ebase + 1) : 0;

        unsigned long long acc[20];              // 2 edges x 10 u64 (20 outputs)
#pragma unroll
        for (int i = 0; i < 20; i++) acc[i] = 0ULL;
        const float* hcol = sX + col;
        const float* wbase = sW2 + p * 20;
#pragma unroll 4
        for (int k = 0; k < 64; k++) {
            float2 hv = *(const float2*)(hcol + k * XSTRIDE);
            unsigned long long x0 = pk2s(hv.x), x1 = pk2s(hv.y);
            const ulonglong2* wr = (const ulonglong2*)(wbase + k * 80);
#pragma unroll
            for (int m = 0; m < 5; m++) {
                ulonglong2 w = wr[m];
                ff2(acc[2*m],      x0, w.x);  ff2(acc[2*m + 1],      x0, w.y);
                ff2(acc[10 + 2*m], x1, w.x);  ff2(acc[10 + 2*m + 1], x1, w.y);
            }
        }
        if (ebase < E) {
            ulonglong2* wp = (ulonglong2*)(g_wf + (size_t)pos0 * 80 + p * 20);
            ulonglong2 s01; s01.x = acc[0]; s01.y = acc[1];
            ulonglong2 s23; s23.x = acc[2]; s23.y = acc[3];
            wp[0] = s01; wp[1] = s23;
            ((unsigned long long*)wp)[4] = acc[4];
        }
        if (ebase + 1 < E) {
            ulonglong2* wp = (ulonglong2*)(g_wf + (size_t)pos1 * 80 + p * 20);
            ulonglong2 s01; s01.x = acc[10]; s01.y = acc[11];
            ulonglong2 s23; s23.x = acc[12]; s23.y = acc[13];
            wp[0] = s01; wp[1] = s23;
            ((unsigned long long*)wp)[4] = acc[14];
        }
    }
}

// ======================================================================
// Kernel: self-interaction s = FCTP(x, attr; W_si)
// ======================================================================
__global__ void __launch_bounds__(128) node_pre_kernel(
    const float* __restrict__ xin, const float* __restrict__ attr,
    const float* __restrict__ Wsi0, const float* __restrict__ Wsi1, int N)
{
    __shared__ float w0[256], w1[256];
    int t = threadIdx.x;
    if (t < 128) { w0[t] = Wsi0[t]; w0[t + 128] = Wsi0[t + 128];
                   w1[t] = Wsi1[t]; w1[t + 128] = Wsi1[t + 128]; }
    __syncthreads();
    int n = blockIdx.x * 128 + t;
    if (n >= N) return;

    float x[64];
    const float4* xp = (const float4*)(xin + (size_t)n * 64);
#pragma unroll
    for (int qq = 0; qq < 16; qq++) {
        float4 v = __ldg(xp + qq);
        x[4*qq] = v.x; x[4*qq+1] = v.y; x[4*qq+2] = v.z; x[4*qq+3] = v.w;
    }
    float a = __ldg(attr + n) * 0.25f;  // attr / sqrt(16)

    float out[64];
#pragma unroll
    for (int u = 0; u < 16; u++) {
        float acc = 0.f;
#pragma unroll
        for (int v = 0; v < 16; v++) acc += x[v] * w0[u*16 + v];
        out[u] = acc * a;
    }
#pragma unroll
    for (int u = 0; u < 16; u++) {
        float a0 = 0.f, a1 = 0.f, a2 = 0.f;
#pragma unroll
        for (int v = 0; v < 16; v++) {
            float wv = w1[u*16 + v];
            a0 += x[16 + 3*v + 0] * wv;
            a1 += x[16 + 3*v + 1] * wv;
            a2 += x[16 + 3*v + 2] * wv;
        }
        out[16 + 3*u + 0] = a0 * a;
        out[16 + 3*u + 1] = a1 * a;
        out[16 + 3*u + 2] = a2 * a;
    }
    float4* sp = (float4*)(g_s + (size_t)n * 64);
#pragma unroll
    for (int qq = 0; qq < 16; qq++)
        sp[qq] = make_float4(out[4*qq], out[4*qq+1], out[4*qq+2], out[4*qq+3]);
}

// ======================================================================
// Aggregation: half-warp (16 lanes) per node, fully sequential CSR walk
// ======================================================================
__global__ void __launch_bounds__(256) agg_kernel(int N)
{
    int u = threadIdx.x & 15;
    int node = blockIdx.x * 16 + (threadIdx.x >> 4);

    int beg = 0, end = 0;
    if (node < N) { beg = __ldg(&g_off[node]); end = __ldg(&g_off[node + 1]); }

    const float is3 = 0.57735026918962576f;   // 1/sqrt(3)
    const float is2 = 0.70710678118654752f;   // 1/sqrt(2)

    float m0a = 0.f, m0b = 0.f;
    float A0 = 0.f, A1 = 0.f, A2 = 0.f;
    float B0 = 0.f, B1 = 0.f, B2 = 0.f;
    float C0 = 0.f, C1 = 0.f, C2 = 0.f;

    for (int p = beg; p < end; p++) {
        const float* wfp = g_wf + (size_t)p * 80;
        float w0 = __ldg(wfp + u);
        float w1 = __ldg(wfp + 16 + u);
        float w2 = __ldg(wfp + 32 + u);
        float w3 = __ldg(wfp + 48 + u);
        float w4 = __ldg(wfp + 64 + u) * is2;
        int dst = __ldg(g_dstp + p);
        float4 y = __ldg((const float4*)g_yp + p);
        const float* gs = g_s + (size_t)dst * 64;
        float g0 = __ldg(gs + u);
        float ga = __ldg(gs + 16 + 3*u);
        float gb = __ldg(gs + 17 + 3*u);
        float gc = __ldg(gs + 18 + 3*u);

        m0a += w0 * g0 * y.x;
        m0b += w3 * (ga*y.y + gb*y.z + gc*y.w) * is3;
        float w1g = w1 * g0;
        A0 += w1g * y.y;  A1 += w1g * y.z;  A2 += w1g * y.w;
        float w2y = w2 * y.x;
        B0 += w2y * ga;   B1 += w2y * gb;   B2 += w2y * gc;
        C0 += w4 * (gb * y.w - gc * y.z);
        C1 += w4 * (gc * y.y - ga * y.w);
        C2 += w4 * (ga * y.z - gb * y.y);
    }

    if (node < N) {
        float* ab = g_agg + (size_t)node * 176;
        ab[u]         = m0a;
        ab[16 + u]    = m0b;
        ab[32 + 3*u]  = A0;  ab[33 + 3*u]  = A1;  ab[34 + 3*u]  = A2;
        ab[80 + 3*u]  = B0;  ab[81 + 3*u]  = B1;  ab[82 + 3*u]  = B2;
        ab[128 + 3*u] = C0;  ab[129 + 3*u] = C1;  ab[130 + 3*u] = C2;
    }
}

// ======================================================================
// Kernel: per-node output + re-zero g_deg for the next graph replay
// ======================================================================
__global__ void __launch_bounds__(128) node_post_kernel(
    const float* __restrict__ xin, const float* __restrict__ attr,
    const float* __restrict__ Wsc0, const float* __restrict__ Wsc1,
    const float* __restrict__ Wlo0, const float* __restrict__ Wlo1,
    const float* __restrict__ Wal, float* __restrict__ out, int N)
{
    __shared__ float sc0[256], sc1[256], lo0[512], lo1[768], al[32];
    int t = threadIdx.x;
    for (int i = t; i < 256; i += 128) { sc0[i] = Wsc0[i]; sc1[i] = Wsc1[i]; }
    for (int i = t; i < 512; i += 128) lo0[i] = Wlo0[i];
    for (int i = t; i < 768; i += 128) lo1[i] = Wlo1[i];
    if (t < 32) al[t] = Wal[t];
    __syncthreads();

    int n = blockIdx.x * 128 + t;
    if (n >= N) return;

    g_deg[n] = 0;   // invariant for next replay (globals start zeroed)

    const float* ag = g_agg + (size_t)n * 176;
    float o0[16], o1[48];
#pragma unroll
    for (int u = 0; u < 16; u++) o0[u] = 0.f;
#pragma unroll
    for (int j = 0; j < 48; j++) o1[j] = 0.f;
    float alpha = 0.f;

#pragma unroll
    for (int vg = 0; vg < 16; vg += 4) {
        float4 P = __ldg((const float4*)(ag + vg));
        float4 Q = __ldg((const float4*)(ag + 16 + vg));
        const float4* Ap = (const float4*)(ag + 32  + 3*vg);
        const float4* Bp = (const float4*)(ag + 80  + 3*vg);
        const float4* Cp = (const float4*)(ag + 128 + 3*vg);
        float4 Af0 = __ldg(Ap), Af1 = __ldg(Ap+1), Af2 = __ldg(Ap+2);
        float4 Bf0 = __ldg(Bp), Bf1 = __ldg(Bp+1), Bf2 = __ldg(Bp+2);
        float4 Cf0 = __ldg(Cp), Cf1 = __ldg(Cp+1), Cf2 = __ldg(Cp+2);
        float m0aq[4] = {P.x, P.y, P.z, P.w};
        float m0bq[4] = {Q.x, Q.y, Q.z, Q.w};
        float Aq[12] = {Af0.x,Af0.y,Af0.z,Af0.w,Af1.x,Af1.y,Af1.z,Af1.w,Af2.x,Af2.y,Af2.z,Af2.w};
        float Bq[12] = {Bf0.x,Bf0.y,Bf0.z,Bf0.w,Bf1.x,Bf1.y,Bf1.z,Bf1.w,Bf2.x,Bf2.y,Bf2.z,Bf2.w};
        float Cq[12] = {Cf0.x,Cf0.y,Cf0.z,Cf0.w,Cf1.x,Cf1.y,Cf1.z,Cf1.w,Cf2.x,Cf2.y,Cf2.z,Cf2.w};
#pragma unroll
        for (int j = 0; j < 4; j++) {
            int v = vg + j;
            float m0a = m0aq[j] * 0.25f;   // / sqrt(NUM_NEIGHBORS)
            float m0b = m0bq[j] * 0.25f;
            float Ax = Aq[3*j]*0.25f, Ay = Aq[3*j+1]*0.25f, Az = Aq[3*j+2]*0.25f;
            float Bx = Bq[3*j]*0.25f, By = Bq[3*j+1]*0.25f, Bz = Bq[3*j+2]*0.25f;
            float Cx = Cq[3*j]*0.25f, Cy = Cq[3*j+1]*0.25f, Cz = Cq[3*j+2]*0.25f;
            alpha += m0a * al[v] + m0b * al[16 + v];
#pragma unroll
            for (int u = 0; u < 16; u++) {
                o0[u] += m0a * lo0[u*32 + v] + m0b * lo0[u*32 + 16 + v];
                float wa = lo1[u*48 + v], wb = lo1[u*48 + 16 + v], wc = lo1[u*48 + 32 + v];
                o1[u*3 + 0] += Ax * wa + Bx * wb + Cx * wc;
                o1[u*3 + 1] += Ay * wa + By * wb + Cy * wc;
                o1[u*3 + 2] += Az * wa + Bz * wb + Cz * wc;
            }
        }
    }

    float x[64];
    const float4* xp = (const float4*)(xin + (size_t)n * 64);
#pragma unroll
    for (int qq = 0; qq < 16; qq++) {
        float4 v4 = __ldg(xp + qq);
        x[4*qq] = v4.x; x[4*qq+1] = v4.y; x[4*qq+2] = v4.z; x[4*qq+3] = v4.w;
    }
    float a   = __ldg(attr + n);
    float a4  = a * 0.25f;
    float s32 = a * 0.17677669529663689f;
    float s48 = a * 0.14433756729740643f;
    float alphaf = alpha * s32;

    float res[64];
#pragma unroll
    for (int u = 0; u < 16; u++) {
        float sk = 0.f;
#pragma unroll
        for (int v = 0; v < 16; v++) sk += x[v] * sc0[u*16 + v];
        res[u] = o0[u] * s32 * alphaf + sk * a4;
    }
#pragma unroll
    for (int u = 0; u < 16; u++) {
        float sa = 0.f, sb = 0.f, sc = 0.f;
#pragma unroll
        for (int v = 0; v < 16; v++) {
            float wv = sc1[u*16 + v];
            sa += x[16 + 3*v + 0] * wv;
            sb += x[16 + 3*v + 1] * wv;
            sc += x[16 + 3*v + 2] * wv;
        }
        res[16 + 3*u + 0] = o1[3*u + 0] * s48 * alphaf + sa * a4;
        res[16 + 3*u + 1] = o1[3*u + 1] * s48 * alphaf + sb * a4;
        res[16 + 3*u + 2] = o1[3*u + 2] * s48 * alphaf + sc * a4;
    }
    float4* op = (float4*)(out + (size_t)n * 64);
#pragma unroll
    for (int qq = 0; qq < 16; qq++)
        op[qq] = make_float4(res[4*qq], res[4*qq+1], res[4*qq+2], res[4*qq+3]);
}

// ======================================================================
extern "C" void kernel_launch(void* const* d_in, const int* in_sizes, int n_in,
                              void* d_out, int out_size)
{
    const float* node_input = (const float*)d_in[0];
    const float* node_attr  = (const float*)d_in[1];
    const int*   esrc       = (const int*)d_in[2];
    const int*   edst       = (const int*)d_in[3];
    const float* eattr      = (const float*)d_in[4];
    const float* dist       = (const float*)d_in[5];
    const float* Wsi0 = (const float*)d_in[6];
    const float* Wsi1 = (const float*)d_in[7];
    const float* Wsc0 = (const float*)d_in[8];
    const float* Wsc1 = (const float*)d_in[9];
    const float* Wm1  = (const float*)d_in[10];
    const float* Wm2  = (const float*)d_in[11];
    const float* Wlo0 = (const float*)d_in[12];
    const float* Wlo1 = (const float*)d_in[13];
    const float* Wal  = (const float*)d_in[14];

    int N = in_sizes[0] / 64;
    int E = in_sizes[2];

    int smem_bytes = (64 * XSTRIDE + 4096 + 5120) * (int)sizeof(float);  // 103424
    cudaFuncSetAttribute(fused_mlp_kernel, cudaFuncAttributeMaxDynamicSharedMemorySize, smem_bytes);

    hist_kernel<<<(E + 255) / 256, 256>>>(esrc, E);                                   // 0
    scan_kernel<<<1, 1024>>>(N, E);                                                   // 1
    scatter_kernel<<<(E + 255) / 256, 256>>>(esrc, edst, eattr, E);                   // 2
    fused_mlp_kernel<<<(E + TILE_E - 1) / TILE_E, 256, smem_bytes>>>(dist, Wm1, Wm2, E); // 3 (profiled)
    node_pre_kernel<<<(N + 127) / 128, 128>>>(node_input, node_attr, Wsi0, Wsi1, N);  // 4
    agg_kernel<<<(N + 15) / 16, 256>>>(N);                                            // 5
    node_post_kernel<<<(N + 127) / 128, 128>>>(node_input, node_attr, Wsc0, Wsc1,
                                               Wlo0, Wlo1, Wal, (float*)d_out, N);    // 6
}